// round 6
// baseline (speedup 1.0000x reference)
#include <cuda_runtime.h>
#include <cuda_bf16.h>
#include <math.h>
#include <stdint.h>

#define GMM_D 64
#define GMM_K 64
#define BS    128
#define TPB   128

// padded row stride: 136 bf16 = 272 B (rows walk banks in steps of 4 -> ldmatrix conflict-free)
#define RSA 272
#define RSW 272

// smem layout (bytes)
#define OFF_A1 0                          // X' hi : 128 x 136 bf16
#define OFF_A2 (OFF_A1 + 128 * RSA)       // X' lo
#define OFF_W1 (OFF_A2 + 128 * RSA)       // W  hi : 64 x 136 bf16
#define OFF_W2 (OFF_W1 + 64 * RSW)        // W  lo
#define OFF_C  (OFF_W2 + 64 * RSW)        // 64 floats
#define SMEM_TOTAL (OFF_C + 256)          // 104704 B

// ---------------- helpers ----------------
__device__ __forceinline__ uint32_t smem_u32(const void* p) {
    uint32_t a;
    asm("{ .reg .u64 t; cvta.to.shared.u64 t, %1; cvt.u32.u64 %0, t; }" : "=r"(a) : "l"(p));
    return a;
}
__device__ __forceinline__ uint32_t bf16x2_rn(float lo, float hi) {
    uint32_t r;
    asm("cvt.rn.satfinite.bf16x2.f32 %0, %1, %2;" : "=r"(r) : "f"(hi), "f"(lo));
    return r;
}
__device__ __forceinline__ float lof(uint32_t p) { return __uint_as_float(p << 16); }
__device__ __forceinline__ float hif(uint32_t p) { return __uint_as_float(p & 0xffff0000u); }

__device__ __forceinline__ void ldsm4(uint32_t& r0, uint32_t& r1, uint32_t& r2, uint32_t& r3,
                                      uint32_t a) {
    asm volatile("ldmatrix.sync.aligned.m8n8.x4.shared.b16 {%0,%1,%2,%3}, [%4];"
                 : "=r"(r0), "=r"(r1), "=r"(r2), "=r"(r3) : "r"(a));
}
__device__ __forceinline__ void mma16816(float* d, const uint32_t* a, const uint32_t* b) {
    asm volatile(
        "mma.sync.aligned.m16n8k16.row.col.f32.bf16.bf16.f32 "
        "{%0,%1,%2,%3}, {%4,%5,%6,%7}, {%8,%9}, {%0,%1,%2,%3};"
        : "+f"(d[0]), "+f"(d[1]), "+f"(d[2]), "+f"(d[3])
        : "r"(a[0]), "r"(a[1]), "r"(a[2]), "r"(a[3]), "r"(b[0]), "r"(b[1]));
}

// ---------------------------------------------------------------------------
// Fused GMM posterior via HMMA (mma.sync bf16, 3-product fp32 reconstruction).
// GEMM: D[n,c] = sum_j X'[n,j] * W[c,j]
//   X'[n,j<64] = x[n,j],  X'[n,64+j] = x[n,j]^2
//   W[c,j<64]  = mu*e^{-lv},  W[c,64+j] = -0.5*e^{-lv}
//   C[c] = -0.5*sum_d(lv + mu^2 e^{-lv}) + lp[c]  (k-uniform terms cancel in posterior)
// Block: 128 samples x 64 comps. Warp: 32 rows x 64 cols (2 m16 x 8 n8 tiles).
// ---------------------------------------------------------------------------
__global__ void __launch_bounds__(TPB, 2)
gmm_fused(const float* __restrict__ X, const float* __restrict__ mu,
          const float* __restrict__ lv, const float* __restrict__ lp,
          float* __restrict__ out, int N) {
    extern __shared__ char sm[];
    const uint32_t smb = smem_u32(sm);
    const int t  = threadIdx.x;
    const int n0 = blockIdx.x * BS;
    float* sC = (float*)(sm + OFF_C);

    // ---- stage W hi/lo tiles (row c, 136-bf16 padded rows) ----
    {
        #pragma unroll
        for (int i = 0; i < 16; i++) {
            int idx = i * TPB + t;            // 0..2047 pair slots
            int k   = idx >> 5;
            int d   = (idx & 31) * 2;
            float l0 = lv[k * GMM_D + d],  l1 = lv[k * GMM_D + d + 1];
            float m0 = mu[k * GMM_D + d],  m1 = mu[k * GMM_D + d + 1];
            float e0 = __expf(-l0), e1 = __expf(-l1);
            float wa0 = m0 * e0,      wa1 = m1 * e1;       // j = d
            float wb0 = -0.5f * e0,   wb1 = -0.5f * e1;    // j = 64 + d
            uint32_t ah = bf16x2_rn(wa0, wa1);
            uint32_t al = bf16x2_rn(wa0 - lof(ah), wa1 - hif(ah));
            uint32_t bh = bf16x2_rn(wb0, wb1);
            uint32_t bl = bf16x2_rn(wb0 - lof(bh), wb1 - hif(bh));
            char* r1 = sm + OFF_W1 + k * RSW;
            char* r2 = sm + OFF_W2 + k * RSW;
            *(uint32_t*)(r1 + d * 2)       = ah;
            *(uint32_t*)(r1 + 128 + d * 2) = bh;
            *(uint32_t*)(r2 + d * 2)       = al;
            *(uint32_t*)(r2 + 128 + d * 2) = bl;
        }
    }

    // ---- stage X' hi/lo tiles ----
    {
        const float4* xg4 = (const float4*)(X + (size_t)n0 * GMM_D);
        #pragma unroll
        for (int i = 0; i < 16; i++) {
            int idx = i * TPB + t;            // 0..2047 float4 slots
            int n   = idx >> 4;
            int d0  = (idx & 15) * 4;
            float4 v = xg4[idx];
            uint32_t h01 = bf16x2_rn(v.x, v.y);
            uint32_t h23 = bf16x2_rn(v.z, v.w);
            uint32_t l01 = bf16x2_rn(v.x - lof(h01), v.y - hif(h01));
            uint32_t l23 = bf16x2_rn(v.z - lof(h23), v.w - hif(h23));
            float s0 = v.x * v.x, s1 = v.y * v.y, s2 = v.z * v.z, s3 = v.w * v.w;
            uint32_t sh01 = bf16x2_rn(s0, s1);
            uint32_t sh23 = bf16x2_rn(s2, s3);
            uint32_t sl01 = bf16x2_rn(s0 - lof(sh01), s1 - hif(sh01));
            uint32_t sl23 = bf16x2_rn(s2 - lof(sh23), s3 - hif(sh23));
            char* r1 = sm + OFF_A1 + n * RSA;
            char* r2 = sm + OFF_A2 + n * RSA;
            *(uint2*)(r1 + d0 * 2)       = make_uint2(h01, h23);
            *(uint2*)(r1 + 128 + d0 * 2) = make_uint2(sh01, sh23);
            *(uint2*)(r2 + d0 * 2)       = make_uint2(l01, l23);
            *(uint2*)(r2 + 128 + d0 * 2) = make_uint2(sl01, sl23);
        }
    }

    // ---- per-component constant ----
    if (t < GMM_K) {
        float s = 0.f;
        #pragma unroll 8
        for (int d = 0; d < GMM_D; d++) {
            float l = lv[t * GMM_D + d];
            float m = mu[t * GMM_D + d];
            s += l + m * m * __expf(-l);
        }
        sC[t] = -0.5f * s + lp[t];
    }
    __syncthreads();

    // ---- main HMMA loop ----
    const int lane = t & 31;
    const int warp = t >> 5;
    const int gid  = lane >> 2;
    const int tig  = lane & 3;

    // A ldmatrix per-lane address part: rows = lane&15, k-half = lane>>4
    const uint32_t a_base = smb + OFF_A1
                          + (uint32_t)(warp * 32 + (lane & 15)) * RSA
                          + (uint32_t)((lane >> 4) * 16);
    // B ldmatrix per-lane address part: g = lane>>3
    const int g = lane >> 3;
    const uint32_t b_base = smb + OFF_W1
                          + (uint32_t)(((g >> 1) * 8 + (lane & 7))) * RSW
                          + (uint32_t)((g & 1) * 16);

    float acc[2][8][4];
    #pragma unroll
    for (int mi = 0; mi < 2; mi++)
        #pragma unroll
        for (int nt = 0; nt < 8; nt++)
            #pragma unroll
            for (int r = 0; r < 4; r++) acc[mi][nt][r] = 0.f;

    #pragma unroll 1
    for (int ks = 0; ks < 8; ks++) {
        uint32_t a1f[2][4], a2f[2][4];
        #pragma unroll
        for (int mi = 0; mi < 2; mi++) {
            uint32_t aa = a_base + mi * (16 * RSA) + ks * 32;
            ldsm4(a1f[mi][0], a1f[mi][1], a1f[mi][2], a1f[mi][3], aa);
            ldsm4(a2f[mi][0], a2f[mi][1], a2f[mi][2], a2f[mi][3],
                  aa + (OFF_A2 - OFF_A1));
        }
        uint32_t b1f[8][2], b2f[8][2];
        #pragma unroll
        for (int p = 0; p < 4; p++) {
            uint32_t ba = b_base + p * (16 * RSW) + ks * 32;
            ldsm4(b1f[2 * p][0], b1f[2 * p][1], b1f[2 * p + 1][0], b1f[2 * p + 1][1], ba);
            ldsm4(b2f[2 * p][0], b2f[2 * p][1], b2f[2 * p + 1][0], b2f[2 * p + 1][1],
                  ba + (OFF_W2 - OFF_W1));
        }
        #pragma unroll
        for (int mi = 0; mi < 2; mi++)
            #pragma unroll
            for (int nt = 0; nt < 8; nt++) {
                mma16816(acc[mi][nt], a1f[mi], b1f[nt]);   // x1*w1
                mma16816(acc[mi][nt], a1f[mi], b2f[nt]);   // x1*w2
                mma16816(acc[mi][nt], a2f[mi], b1f[nt]);   // x2*w1
            }
    }

    // ---- epilogue: per-row logsumexp via quad shuffles ----
    float ck0[8], ck1[8];
    #pragma unroll
    for (int nt = 0; nt < 8; nt++) {
        ck0[nt] = sC[nt * 8 + 2 * tig];
        ck1[nt] = sC[nt * 8 + 2 * tig + 1];
    }

    #pragma unroll
    for (int mi = 0; mi < 2; mi++) {
        #pragma unroll
        for (int h = 0; h < 2; h++) {
            float v[16];
            float mx = -INFINITY;
            #pragma unroll
            for (int nt = 0; nt < 8; nt++) {
                float v0 = acc[mi][nt][2 * h]     + ck0[nt];
                float v1 = acc[mi][nt][2 * h + 1] + ck1[nt];
                v[2 * nt] = v0; v[2 * nt + 1] = v1;
                mx = fmaxf(mx, fmaxf(v0, v1));
            }
            mx = fmaxf(mx, __shfl_xor_sync(0xffffffffu, mx, 1));
            mx = fmaxf(mx, __shfl_xor_sync(0xffffffffu, mx, 2));
            float s = 0.f;
            #pragma unroll
            for (int i = 0; i < 16; i++) s += __expf(v[i] - mx);
            s += __shfl_xor_sync(0xffffffffu, s, 1);
            s += __shfl_xor_sync(0xffffffffu, s, 2);
            const float lse = mx + __logf(s);

            const int n = n0 + warp * 32 + mi * 16 + h * 8 + gid;
            #pragma unroll
            for (int nt = 0; nt < 8; nt++) {
                out[(size_t)(nt * 8 + 2 * tig)     * N + n] = v[2 * nt]     - lse;
                out[(size_t)(nt * 8 + 2 * tig + 1) * N + n] = v[2 * nt + 1] - lse;
            }
        }
    }
}

extern "C" void kernel_launch(void* const* d_in, const int* in_sizes, int n_in,
                              void* d_out, int out_size) {
    const float* X  = (const float*)d_in[0];
    const float* mu = (const float*)d_in[1];
    const float* lv = (const float*)d_in[2];
    const float* lp = (const float*)d_in[3];
    float* out = (float*)d_out;

    const int K = in_sizes[3];            // 64
    const int D = in_sizes[1] / K;        // 64
    const int N = in_sizes[0] / D;        // 131072

    cudaFuncSetAttribute(gmm_fused, cudaFuncAttributeMaxDynamicSharedMemorySize, SMEM_TOTAL);
    gmm_fused<<<N / BS, TPB, SMEM_TOTAL>>>(X, mu, lv, lp, out, N);
}